// round 10
// baseline (speedup 1.0000x reference)
#include <cuda_runtime.h>
#include <cstdint>

// Cumulative matrix product (associative scan of matmul) over axis 1.
// input:  (32, 256, 128, 128) fp32
// output: x (32,128,128) followed by all_outputs (32,256,128,128), flat.
//
// Chunked scan (4 passes). Matmul core: fp16 m16n8k16 MMA, 3-term split
// (hh+lh+hl). A is split once and kept resident in smem for the whole
// matmul; B streams through double-buffered K=32 slabs with ONE barrier per
// slab. In pass1 chains, the epilogue splits the accumulators directly into
// the resident A tiles (no global A round-trip).

#define DN 128
#define BATCH 32
#define SEQ 256
#define CH 16
#define CL 16

#define AROWB 272u   // bytes per smem row: 128 halves + 8 pad (conflict-free ldmatrix)
#define OFF_AH 0u
#define OFF_AL 34816u
#define OFF_BH0 69632u
#define OFF_BL0 78336u
#define OFF_BH1 87040u
#define OFF_BL1 95744u
#define SMEM_SZ 104448

__device__ float g_scr0[(size_t)BATCH * CH * DN * DN];
__device__ float g_scr1[(size_t)BATCH * CH * DN * DN];

__device__ __forceinline__ unsigned smem_u32(const void* p) {
    unsigned a;
    asm("{ .reg .u64 t; cvta.to.shared.u64 t, %1; cvt.u32.u64 %0, t; }" : "=r"(a) : "l"(p));
    return a;
}
// pack two f32 -> half2 {x:low, y:high}
__device__ __forceinline__ unsigned pack2h(float lo, float hi) {
    unsigned r;
    asm("cvt.rn.f16x2.f32 %0, %1, %2;" : "=r"(r) : "f"(hi), "f"(lo));
    return r;
}
__device__ __forceinline__ float2 h2f(unsigned h) {
    float2 f;
    asm("{ .reg .f16 a, b;\n\t mov.b32 {a, b}, %2;\n\t"
        " cvt.f32.f16 %0, a;\n\t cvt.f32.f16 %1, b; }"
        : "=f"(f.x), "=f"(f.y) : "r"(h));
    return f;
}
__device__ __forceinline__ void split4(float4 v, unsigned& h0, unsigned& h1,
                                       unsigned& l0, unsigned& l1) {
    h0 = pack2h(v.x, v.y);
    h1 = pack2h(v.z, v.w);
    float2 f0 = h2f(h0), f1 = h2f(h1);
    l0 = pack2h(v.x - f0.x, v.y - f0.y);
    l1 = pack2h(v.z - f1.x, v.w - f1.y);
}
__device__ __forceinline__ void ldsm4(unsigned r[4], unsigned addr) {
    asm volatile("ldmatrix.sync.aligned.m8n8.x4.shared.b16 {%0,%1,%2,%3}, [%4];"
                 : "=r"(r[0]), "=r"(r[1]), "=r"(r[2]), "=r"(r[3]) : "r"(addr));
}
__device__ __forceinline__ void ldsm4t(unsigned r[4], unsigned addr) {
    asm volatile("ldmatrix.sync.aligned.m8n8.x4.trans.shared.b16 {%0,%1,%2,%3}, [%4];"
                 : "=r"(r[0]), "=r"(r[1]), "=r"(r[2]), "=r"(r[3]) : "r"(addr));
}
__device__ __forceinline__ void mma16(float c[4], const unsigned a[4],
                                      unsigned b0, unsigned b1) {
    asm volatile(
        "mma.sync.aligned.m16n8k16.row.col.f32.f16.f16.f32 "
        "{%0,%1,%2,%3},{%4,%5,%6,%7},{%8,%9},{%0,%1,%2,%3};"
        : "+f"(c[0]), "+f"(c[1]), "+f"(c[2]), "+f"(c[3])
        : "r"(a[0]), "r"(a[1]), "r"(a[2]), "r"(a[3]), "r"(b0), "r"(b1));
}

__device__ __forceinline__ void copy128(const float* __restrict__ s, float* __restrict__ d) {
    const float4* s4 = (const float4*)s;
    float4* d4 = (float4*)d;
#pragma unroll
    for (int i = threadIdx.x; i < DN * DN / 4; i += 256) d4[i] = s4[i];
}

// prefetch one K=32 B slab (16 floats/thread)
__device__ __forceinline__ void prefB(const float* __restrict__ B, int k0, int tid,
                                      float4 r[4]) {
#pragma unroll
    for (int i = 0; i < 4; i++) {
        int f = tid + 256 * i;
        int rr = f >> 5, c4 = (f & 31) * 4;
        r[i] = *(const float4*)&B[(size_t)(k0 + rr) * DN + c4];
    }
}
__device__ __forceinline__ void storeB(char* sm, unsigned offH, unsigned offL, int tid,
                                       const float4 r[4]) {
#pragma unroll
    for (int i = 0; i < 4; i++) {
        int f = tid + 256 * i;
        int rr = f >> 5, c4 = (f & 31) * 4;
        unsigned h0, h1, l0, l1;
        split4(r[i], h0, h1, l0, l1);
        *(uint2*)(sm + offH + rr * AROWB + c4 * 2) = make_uint2(h0, h1);
        *(uint2*)(sm + offL + rr * AROWB + c4 * 2) = make_uint2(l0, l1);
    }
}

// 256 threads (8 warps, 64x32 warp tiles): C = A @ B (128x128 row-major fp32).
// ARES: A hi/lo tiles already resident in smem (left by prior CHAIN epilogue).
// CHAIN: epilogue also splits acc into the resident A tiles for the next call.
// C may alias B: all B global reads precede the final barrier; C stores follow.
template <bool ARES, bool CHAIN>
__device__ __forceinline__ void mm128(const float* __restrict__ A,
                                      const float* __restrict__ B,
                                      float* __restrict__ C) {
    extern __shared__ char sm[];
    const int tid = threadIdx.x;
    const int lane = tid & 31, w = tid >> 5;
    const int wm = (w >> 2) * 64, wn = (w & 3) * 32;
    const unsigned smb = smem_u32(sm);
    const unsigned loff = (unsigned)(((lane & 7) + (lane & 8)) * AROWB + (lane >> 4) * 16);

    float acc[4][4][4];
#pragma unroll
    for (int mt = 0; mt < 4; mt++)
#pragma unroll
        for (int nt = 0; nt < 4; nt++)
#pragma unroll
            for (int i = 0; i < 4; i++) acc[mt][nt][i] = 0.0f;

    float4 rb[4];
    prefB(B, 0, tid, rb);   // B slab 0 in flight during A prologue

    if (!ARES) {
        __syncthreads();  // orders prior copy/epilogue stores before A tile overwrite
#pragma unroll
        for (int i = 0; i < 16; i++) {
            int f = tid + 256 * i;
            int r = f >> 5, c4 = (f & 31) * 4;
            float4 v = *(const float4*)&A[(size_t)r * DN + c4];
            unsigned h0, h1, l0, l1;
            split4(v, h0, h1, l0, l1);
            *(uint2*)(sm + OFF_AH + r * AROWB + c4 * 2) = make_uint2(h0, h1);
            *(uint2*)(sm + OFF_AL + r * AROWB + c4 * 2) = make_uint2(l0, l1);
        }
    } else {
        (void)A;
    }

#pragma unroll
    for (int s = 0; s < 4; s++) {
        const unsigned obh = (s & 1) ? OFF_BH1 : OFF_BH0;
        const unsigned obl = (s & 1) ? OFF_BL1 : OFF_BL0;
        storeB(sm, obh, obl, tid, rb);
        __syncthreads();  // buf[s&1] + (s==0: A tiles) visible; prev MMAs done
        if (s < 3) prefB(B, (s + 1) * 32, tid, rb);
#pragma unroll
        for (int t = 0; t < 3; t++) {
            const unsigned aB = smb + ((t == 1) ? OFF_AL : OFF_AH);
            const unsigned bB = smb + ((t == 2) ? obl : obh);
#pragma unroll
            for (int kk = 0; kk < 32; kk += 16) {
                unsigned af[4][4];
#pragma unroll
                for (int mt = 0; mt < 4; mt++)
                    ldsm4(af[mt], aB + (unsigned)((wm + mt * 16) * AROWB + (s * 32 + kk) * 2) + loff);
                unsigned bf[2][4];
#pragma unroll
                for (int np = 0; np < 2; np++)
                    ldsm4t(bf[np], bB + (unsigned)(kk * AROWB + (wn + np * 16) * 2) + loff);
#pragma unroll
                for (int mt = 0; mt < 4; mt++)
#pragma unroll
                    for (int nt = 0; nt < 4; nt++)
                        mma16(acc[mt][nt], af[mt], bf[nt >> 1][(nt & 1) * 2],
                              bf[nt >> 1][(nt & 1) * 2 + 1]);
            }
        }
    }
    __syncthreads();  // all MMAs/ldsm done: safe to store C & overwrite A tiles

    // epilogue: store C (fp32), optionally split acc into resident A tiles
#pragma unroll
    for (int mt = 0; mt < 4; mt++)
#pragma unroll
        for (int nt = 0; nt < 4; nt++) {
            const int r0 = wm + mt * 16 + (lane >> 2);
            const int c0 = wn + nt * 8 + (lane & 3) * 2;
            *(float2*)&C[(size_t)r0 * DN + c0] = make_float2(acc[mt][nt][0], acc[mt][nt][1]);
            *(float2*)&C[(size_t)(r0 + 8) * DN + c0] = make_float2(acc[mt][nt][2], acc[mt][nt][3]);
            if (CHAIN) {
                unsigned h = pack2h(acc[mt][nt][0], acc[mt][nt][1]);
                float2 f = h2f(h);
                unsigned l = pack2h(acc[mt][nt][0] - f.x, acc[mt][nt][1] - f.y);
                *(unsigned*)(sm + OFF_AH + r0 * AROWB + c0 * 2) = h;
                *(unsigned*)(sm + OFF_AL + r0 * AROWB + c0 * 2) = l;
                h = pack2h(acc[mt][nt][2], acc[mt][nt][3]);
                f = h2f(h);
                l = pack2h(acc[mt][nt][2] - f.x, acc[mt][nt][3] - f.y);
                *(unsigned*)(sm + OFF_AH + (r0 + 8) * AROWB + c0 * 2) = h;
                *(unsigned*)(sm + OFF_AL + (r0 + 8) * AROWB + c0 * 2) = l;
            }
        }
}

// Pass 1: local prefix products within each chunk (A chained through smem).
__global__ void __launch_bounds__(256, 2) k_pass1(const float* __restrict__ in,
                                                  float* __restrict__ outAll) {
    const int b = blockIdx.x / CH, c = blockIdx.x % CH;
    const size_t MM = (size_t)DN * DN;
    const size_t base = ((size_t)b * SEQ + (size_t)c * CL) * MM;
    const float* E = in + base;
    float* O = outAll + base;
    copy128(E, O);
    mm128<false, true>(O, E + MM, O + MM);
#pragma unroll 1
    for (int j = 2; j < CL - 1; j++)
        mm128<true, true>(nullptr, E + (size_t)j * MM, O + (size_t)j * MM);
    mm128<true, false>(nullptr, E + (size_t)(CL - 1) * MM, O + (size_t)(CL - 1) * MM);
}

// Pass 2 step (Hillis-Steele over chunk totals).
__global__ void __launch_bounds__(256, 2) k_scan(const float* __restrict__ src,
                                                 size_t soff, size_t sb, size_t si,
                                                 float* __restrict__ dst, int d) {
    const int b = blockIdx.x / CH, i = blockIdx.x % CH;
    const float* Ti = src + soff + (size_t)b * sb + (size_t)i * si;
    float* Dp = dst + ((size_t)b * CH + i) * ((size_t)DN * DN);
    if (i < d) { copy128(Ti, Dp); return; }
    mm128<false, false>(src + soff + (size_t)b * sb + (size_t)(i - d) * si, Ti, Dp);
}

// Pass 3: apply exclusive chunk prefix to chunks 1..CH-1 (in place).
__global__ void __launch_bounds__(256, 2) k_pass3(float* __restrict__ outAll,
                                                  const float* __restrict__ scan) {
    int idx = blockIdx.x;
    const int j = idx % CL; idx /= CL;
    const int c = (idx % (CH - 1)) + 1; idx /= (CH - 1);
    const int b = idx;
    const float* A = scan + ((size_t)b * CH + (c - 1)) * ((size_t)DN * DN);
    float* Bp = outAll + ((size_t)b * SEQ + (size_t)c * CL + j) * ((size_t)DN * DN);
    mm128<false, false>(A, Bp, Bp);
}

// Pass 4: x[b] = all_outputs[b, SEQ-1]
__global__ void __launch_bounds__(256) k_copy_x(const float* __restrict__ outAll,
                                                float* __restrict__ x) {
    copy128(outAll + ((size_t)blockIdx.x * SEQ + (SEQ - 1)) * (DN * DN),
            x + (size_t)blockIdx.x * DN * DN);
}

extern "C" void kernel_launch(void* const* d_in, const int* in_sizes, int n_in,
                              void* d_out, int out_size) {
    const float* in = (const float*)d_in[0];
    float* out = (float*)d_out;
    float* x = out;                                  // first 32*128*128 elements
    float* outAll = out + (size_t)BATCH * DN * DN;   // then 32*256*128*128

    float *scr0, *scr1;
    cudaGetSymbolAddress((void**)&scr0, g_scr0);
    cudaGetSymbolAddress((void**)&scr1, g_scr1);

    cudaFuncSetAttribute(k_pass1, cudaFuncAttributeMaxDynamicSharedMemorySize, SMEM_SZ);
    cudaFuncSetAttribute(k_scan, cudaFuncAttributeMaxDynamicSharedMemorySize, SMEM_SZ);
    cudaFuncSetAttribute(k_pass3, cudaFuncAttributeMaxDynamicSharedMemorySize, SMEM_SZ);

    const size_t MM = (size_t)DN * DN;

    k_pass1<<<BATCH * CH, 256, SMEM_SZ>>>(in, outAll);
    k_scan<<<BATCH * CH, 256, SMEM_SZ>>>(outAll, (size_t)(CL - 1) * MM,
                                         (size_t)SEQ * MM, (size_t)CL * MM, scr0, 1);
    k_scan<<<BATCH * CH, 256, SMEM_SZ>>>(scr0, 0, (size_t)CH * MM, MM, scr1, 2);
    k_scan<<<BATCH * CH, 256, SMEM_SZ>>>(scr1, 0, (size_t)CH * MM, MM, scr0, 4);
    k_scan<<<BATCH * CH, 256, SMEM_SZ>>>(scr0, 0, (size_t)CH * MM, MM, scr1, 8);
    k_pass3<<<BATCH * (CH - 1) * CL, 256, SMEM_SZ>>>(outAll, scr1);
    k_copy_x<<<BATCH, 256>>>(outAll, x);
}